// round 9
// baseline (speedup 1.0000x reference)
#include <cuda_runtime.h>
#include <cstdint>

// Torch_SINDy streaming kernel, R9: cp.async (LDGSTS) staging.
// R8 lesson: per-thread MLP and occupancy trade through the register file
// (16 float4 live -> 54 regs -> occ 50% -> regression). cp.async stages
// gmem->smem with ZERO destination registers: keeps MLP=8/thread while
// dropping live regs to ~28. Thread-private staging -> no __syncthreads.
// .cg bypasses L1 (no wavefront-queue pressure from the front batch).

#define ITEMS 8
#define THREADS 128
#define CHUNK (THREADS * ITEMS)   // 1024 rows per block

__device__ __forceinline__ float sindy_row(float4 v, const float* c) {
    float u  = v.x;
    float u2 = u * u;
    float u3 = u2 * u;
    float y = v.y, z = v.z, w = v.w;
    float r = u * c[0] + u2 * c[1] + u3 * c[2]
            + y * c[3] + z * c[4] + w * c[5];
    r += y * (u * c[6]  + u2 * c[7]  + u3 * c[8]);
    r += z * (u * c[9]  + u2 * c[10] + u3 * c[11]);
    r += w * (u * c[12] + u2 * c[13] + u3 * c[14]);
    return r;
}

__device__ __forceinline__ void load_coeffs(const float* __restrict__ coeff,
                                            const float* __restrict__ base,
                                            float* c) {
    const float4* c4 = (const float4*)coeff;
    const float4* b4 = (const float4*)base;
#pragma unroll
    for (int q = 0; q < 3; ++q) {
        float4 cv = __ldg(&c4[q]);
        float4 bv = __ldg(&b4[q]);
        c[q*4+0] = cv.x * bv.x;
        c[q*4+1] = cv.y * bv.y;
        c[q*4+2] = cv.z * bv.z;
        c[q*4+3] = cv.w * bv.w;
    }
#pragma unroll
    for (int q = 12; q < 15; ++q)
        c[q] = __ldg(&coeff[q]) * __ldg(&base[q]);
}

// Exact path: grid covers n exactly. 8 cp.async.cg 16B copies per thread
// (register-free MLP=8), wait, then per-row LDS.128 readback + compute + STG.
__global__ void __launch_bounds__(THREADS)
sindy_kernel_exact(const float4* __restrict__ big_u,
                   const float*  __restrict__ coeff,
                   const float*  __restrict__ base,
                   float*        __restrict__ out) {
    __shared__ float4 buf[ITEMS][THREADS];   // 16 KB

    float c[15];
    load_coeffs(coeff, base, c);

    int base_i = blockIdx.x * CHUNK + threadIdx.x;

    // Stage 8 coalesced batches gmem->smem, no registers held.
    uint32_t s0 = (uint32_t)__cvta_generic_to_shared(&buf[0][threadIdx.x]);
#pragma unroll
    for (int k = 0; k < ITEMS; ++k) {
        const float4* g = &big_u[base_i + k * THREADS];
        uint32_t s = s0 + (uint32_t)(k * THREADS * sizeof(float4));
        asm volatile("cp.async.cg.shared.global [%0], [%1], 16;\n"
                     :: "r"(s), "l"(g) : "memory");
    }
    asm volatile("cp.async.commit_group;\n" ::: "memory");
    asm volatile("cp.async.wait_group 0;\n" ::: "memory");
    // Thread-private staging: each thread reads only what it wrote -> no bar.

#pragma unroll
    for (int k = 0; k < ITEMS; ++k) {
        float4 v = buf[k][threadIdx.x];
        __stcs(&out[base_i + k * THREADS], sindy_row(v, c));
    }
}

// Guarded tail for arbitrary n.
__global__ void __launch_bounds__(THREADS)
sindy_tail(const float4* __restrict__ big_u,
           const float*  __restrict__ coeff,
           const float*  __restrict__ base,
           float*        __restrict__ out,
           int start, int n) {
    float c[15];
    load_coeffs(coeff, base, c);
    int i = start + blockIdx.x * THREADS + threadIdx.x;
    if (i < n) {
        float4 v = __ldcs(&big_u[i]);
        __stcs(&out[i], sindy_row(v, c));
    }
}

extern "C" void kernel_launch(void* const* d_in, const int* in_sizes, int n_in,
                              void* d_out, int out_size) {
    const float4* big_u = (const float4*)d_in[0];   // [N,4] f32
    const float*  coeff = (const float*)d_in[1];    // [15]  f32
    const float*  base  = (const float*)d_in[2];    // [15]  f32
    float* out = (float*)d_out;                     // [N,1] f32

    int n = in_sizes[0] / 4;   // rows
    int n_full = n / CHUNK;

    if (n_full > 0)
        sindy_kernel_exact<<<n_full, THREADS>>>(big_u, coeff, base, out);

    int tail_start = n_full * CHUNK;
    int tail = n - tail_start;
    if (tail > 0) {
        int tblocks = (tail + THREADS - 1) / THREADS;
        sindy_tail<<<tblocks, THREADS>>>(big_u, coeff, base, out, tail_start, n);
    }
}

// round 10
// speedup vs baseline: 1.0667x; 1.0667x over previous
#include <cuda_runtime.h>

// Torch_SINDy streaming kernel, R10.
// Champion structure = R7 (one-shot, 128-thr blocks, block-strided MLP=8,
// 76.5% DRAM). R10 fixes a pure ordering defect: R7 issued 12 coefficient
// LDGs + FMULs BEFORE the 8 data LDG.128s, delaying each block's DRAM
// traffic by the prologue latency (repaid every block-wave, ~54/SM).
// Data loads now issue first; coeff loads complete under their shadow.

#define ITEMS 8
#define THREADS 128
#define CHUNK (THREADS * ITEMS)   // 1024 rows per block

__device__ __forceinline__ float sindy_row(float4 v, const float* c) {
    float u  = v.x;
    float u2 = u * u;
    float u3 = u2 * u;
    float y = v.y, z = v.z, w = v.w;
    float r = u * c[0] + u2 * c[1] + u3 * c[2]
            + y * c[3] + z * c[4] + w * c[5];
    r += y * (u * c[6]  + u2 * c[7]  + u3 * c[8]);
    r += z * (u * c[9]  + u2 * c[10] + u3 * c[11]);
    r += w * (u * c[12] + u2 * c[13] + u3 * c[14]);
    return r;
}

__device__ __forceinline__ void load_coeffs(const float* __restrict__ coeff,
                                            const float* __restrict__ base,
                                            float* c) {
    const float4* c4 = (const float4*)coeff;
    const float4* b4 = (const float4*)base;
#pragma unroll
    for (int q = 0; q < 3; ++q) {
        float4 cv = __ldg(&c4[q]);
        float4 bv = __ldg(&b4[q]);
        c[q*4+0] = cv.x * bv.x;
        c[q*4+1] = cv.y * bv.y;
        c[q*4+2] = cv.z * bv.z;
        c[q*4+3] = cv.w * bv.w;
    }
#pragma unroll
    for (int q = 12; q < 15; ++q)
        c[q] = __ldg(&coeff[q]) * __ldg(&base[q]);
}

// Exact path: grid covers n exactly, no guards.
// Order: 8 front-batched data LDG.128 FIRST, then coeff loads under their
// DRAM-latency shadow, then compute + store.
__global__ void __launch_bounds__(THREADS)
sindy_kernel_exact(const float4* __restrict__ big_u,
                   const float*  __restrict__ coeff,
                   const float*  __restrict__ base,
                   float*        __restrict__ out) {
    int base_i = blockIdx.x * CHUNK + threadIdx.x;

    float4 v[ITEMS];
#pragma unroll
    for (int k = 0; k < ITEMS; ++k)
        v[k] = __ldcs(&big_u[base_i + k * THREADS]);

    // Coefficient loads + products overlap the in-flight data loads.
    float c[15];
    load_coeffs(coeff, base, c);

#pragma unroll
    for (int k = 0; k < ITEMS; ++k)
        out[base_i + k * THREADS] = sindy_row(v[k], c);
}

// Guarded tail for arbitrary n.
__global__ void __launch_bounds__(THREADS)
sindy_tail(const float4* __restrict__ big_u,
           const float*  __restrict__ coeff,
           const float*  __restrict__ base,
           float*        __restrict__ out,
           int start, int n) {
    int i = start + blockIdx.x * THREADS + threadIdx.x;
    float c[15];
    load_coeffs(coeff, base, c);
    if (i < n) {
        float4 v = __ldcs(&big_u[i]);
        out[i] = sindy_row(v, c);
    }
}

extern "C" void kernel_launch(void* const* d_in, const int* in_sizes, int n_in,
                              void* d_out, int out_size) {
    const float4* big_u = (const float4*)d_in[0];   // [N,4] f32
    const float*  coeff = (const float*)d_in[1];    // [15]  f32
    const float*  base  = (const float*)d_in[2];    // [15]  f32
    float* out = (float*)d_out;                     // [N,1] f32

    int n = in_sizes[0] / 4;   // rows
    int n_full = n / CHUNK;

    if (n_full > 0)
        sindy_kernel_exact<<<n_full, THREADS>>>(big_u, coeff, base, out);

    int tail_start = n_full * CHUNK;
    int tail = n - tail_start;
    if (tail > 0) {
        int tblocks = (tail + THREADS - 1) / THREADS;
        sindy_tail<<<tblocks, THREADS>>>(big_u, coeff, base, out, tail_start, n);
    }
}